// round 6
// baseline (speedup 1.0000x reference)
#include <cuda_runtime.h>
#include <cuda_bf16.h>
#include <math.h>
#include <stdint.h>

// Problem constants
#define BB 2
#define TT 2048
#define DD 1024
#define HH 16
#define DH 64
#define FFN 4096
#define MROWS (BB*TT)          // 4096
#define LN_EPS 1e-3f

// GEMM tiling
#define BM 128
#define BN 128
#define BKK 32
#define ASTR 36                 // padded stride for As [BM][ASTR]
#define BSTR 132                // padded stride for Bs [BKK][BSTR]
#define STAGE_FLOATS (BM*ASTR + BKK*BSTR)   // 4608 + 4224 = 8832
#define GEMM_SMEM (2*STAGE_FLOATS*4)        // 70656 bytes

// ---------------------------------------------------------------------------
// Scratch (device globals; no allocation allowed)
// ---------------------------------------------------------------------------
__device__ float g_xn  [MROWS*DD];
__device__ float g_q   [MROWS*DD];
__device__ float g_k   [MROWS*DD];
__device__ float g_v   [MROWS*DD];
__device__ float g_res1[MROWS*DD];
__device__ float g_h1n [MROWS*DD];
__device__ float g_ff  [MROWS*FFN];
__device__ float g_res2[MROWS*DD];
// tf32-rounded weight copies
__device__ float g_wq_t[DD*DD];
__device__ float g_wk_t[DD*DD];
__device__ float g_wv_t[DD*DD];
__device__ float g_w1_t[DD*FFN];
__device__ float g_w2_t[FFN*DD];

// ---------------------------------------------------------------------------
// Helpers
// ---------------------------------------------------------------------------
__device__ __forceinline__ float f2tf32(float x) {
    uint32_t u;
    asm("cvt.rna.tf32.f32 %0, %1;" : "=r"(u) : "f"(x));
    return __uint_as_float(u);
}

__device__ __forceinline__ void cp16(float* dst, const float* src) {
    unsigned s = (unsigned)__cvta_generic_to_shared(dst);
    asm volatile("cp.async.cg.shared.global [%0], [%1], 16;" :: "r"(s), "l"(src));
}

#define MMA_TF32(c, a, b) \
    asm volatile("mma.sync.aligned.m16n8k8.row.col.f32.tf32.tf32.f32 " \
        "{%0,%1,%2,%3}, {%4,%5,%6,%7}, {%8,%9}, {%0,%1,%2,%3};" \
        : "+f"((c)[0]), "+f"((c)[1]), "+f"((c)[2]), "+f"((c)[3]) \
        : "r"((a)[0]), "r"((a)[1]), "r"((a)[2]), "r"((a)[3]), \
          "r"((b)[0]), "r"((b)[1]))

// ---------------------------------------------------------------------------
// Weight -> tf32 (rna) conversion, elementwise
// ---------------------------------------------------------------------------
__global__ void cvt_tf32_kernel(const float* __restrict__ in,
                                float* __restrict__ outp, int n4) {
    int i = blockIdx.x * blockDim.x + threadIdx.x;
    if (i < n4) {
        float4 v = reinterpret_cast<const float4*>(in)[i];
        v.x = f2tf32(v.x); v.y = f2tf32(v.y);
        v.z = f2tf32(v.z); v.w = f2tf32(v.w);
        reinterpret_cast<float4*>(outp)[i] = v;
    }
}

// ---------------------------------------------------------------------------
// LayerNorm over last dim (D=1024), one block of 256 threads per row.
// Optionally rounds output to tf32 (when output feeds only a GEMM).
// ---------------------------------------------------------------------------
__device__ __forceinline__ float block_reduce_sum_256(float v, float* red) {
    __syncthreads();
#pragma unroll
    for (int o = 16; o > 0; o >>= 1) v += __shfl_xor_sync(0xffffffffu, v, o);
    int lane = threadIdx.x & 31, wid = threadIdx.x >> 5;
    if (lane == 0) red[wid] = v;
    __syncthreads();
    if (wid == 0) {
        v = (lane < 8) ? red[lane] : 0.f;
#pragma unroll
        for (int o = 4; o > 0; o >>= 1) v += __shfl_xor_sync(0xffffffffu, v, o);
        if (lane == 0) red[0] = v;
    }
    __syncthreads();
    return red[0];
}

__global__ void ln1024_kernel(const float* __restrict__ x,
                              const float* __restrict__ gamma,
                              const float* __restrict__ beta,
                              float* __restrict__ out,
                              int tf32out) {
    __shared__ float red[8];
    int row = blockIdx.x;
    int t = threadIdx.x;
    const float4 v = reinterpret_cast<const float4*>(x + (size_t)row * DD)[t];

    float s = v.x + v.y + v.z + v.w;
    float mu = block_reduce_sum_256(s, red) * (1.0f / DD);

    float dx = v.x - mu, dy = v.y - mu, dz = v.z - mu, dw = v.w - mu;
    float q = dx*dx + dy*dy + dz*dz + dw*dw;
    float var = block_reduce_sum_256(q, red) * (1.0f / DD);
    float r = rsqrtf(var + LN_EPS);

    const float4 gg = reinterpret_cast<const float4*>(gamma)[t];
    const float4 bb = reinterpret_cast<const float4*>(beta)[t];
    float4 o;
    o.x = dx * r * gg.x + bb.x;
    o.y = dy * r * gg.y + bb.y;
    o.z = dz * r * gg.z + bb.z;
    o.w = dw * r * gg.w + bb.w;
    if (tf32out) {
        o.x = f2tf32(o.x); o.y = f2tf32(o.y);
        o.z = f2tf32(o.z); o.w = f2tf32(o.w);
    }
    reinterpret_cast<float4*>(out + (size_t)row * DD)[t] = o;
}

// ---------------------------------------------------------------------------
// TF32 tensor-core GEMM core.
// C[M,N] = A[M,K] @ B[K,N] + bias (+relu) (+resid) (+cvt_out to tf32)
// Inputs A,B must already be tf32-rounded bit patterns stored as float.
// 128x128x32 block tile, 256 threads, warp tile 64x32, m16n8k8 mma.
// ---------------------------------------------------------------------------
__device__ __forceinline__ void gemm_prefetch(const float* __restrict__ A,
                                              const float* __restrict__ B,
                                              int K, int N, int bm0, int bn0,
                                              int kt, float* As, float* Bs,
                                              int tid) {
#pragma unroll
    for (int i = 0; i < 4; i++) {
        int lin = tid + i * 256;               // 0..1023
        int row = lin >> 3, c4 = (lin & 7) << 2;
        cp16(As + row * ASTR + c4,
             A + (size_t)(bm0 + row) * K + (size_t)kt * BKK + c4);
    }
#pragma unroll
    for (int i = 0; i < 4; i++) {
        int lin = tid + i * 256;
        int k = lin >> 5, n4 = (lin & 31) << 2;
        cp16(Bs + k * BSTR + n4,
             B + (size_t)(kt * BKK + k) * N + bn0 + n4);
    }
}

__device__ __forceinline__ void gemm_core(int M, int N, int K,
    const float* __restrict__ A, const float* __restrict__ B,
    const float* __restrict__ bias, const float* __restrict__ resid,
    float* __restrict__ C, int relu, int cvt_out) {
    extern __shared__ float sm[];
    const int tid = threadIdx.x;
    const int warp = tid >> 5, lane = tid & 31;
    const int g = lane >> 2, t = lane & 3;
    const int wm0 = (warp & 1) << 6;           // 0 or 64
    const int wn0 = (warp >> 1) << 5;          // 0,32,64,96
    const int bm0 = blockIdx.y * BM, bn0 = blockIdx.x * BN;

    float acc[4][4][4];
#pragma unroll
    for (int i = 0; i < 4; i++)
#pragma unroll
        for (int j = 0; j < 4; j++)
#pragma unroll
            for (int r = 0; r < 4; r++) acc[i][j][r] = 0.f;

    const int nkt = K / BKK;
    gemm_prefetch(A, B, K, N, bm0, bn0, 0, sm, sm + BM * ASTR, tid);
    asm volatile("cp.async.commit_group;");

    int buf = 0;
    for (int kt = 0; kt < nkt; kt++) {
        asm volatile("cp.async.wait_group 0;");
        __syncthreads();
        if (kt + 1 < nkt) {
            float* As_n = sm + (buf ^ 1) * STAGE_FLOATS;
            gemm_prefetch(A, B, K, N, bm0, bn0, kt + 1, As_n,
                          As_n + BM * ASTR, tid);
            asm volatile("cp.async.commit_group;");
        }
        const float* As = sm + buf * STAGE_FLOATS;
        const float* Bs = As + BM * ASTR;
#pragma unroll
        for (int ks = 0; ks < 4; ks++) {
            const int kk = ks * 8;
            unsigned av[4][4], bv[4][2];
#pragma unroll
            for (int mt = 0; mt < 4; mt++) {
                const float* ap = As + (wm0 + mt * 16 + g) * ASTR + kk + t;
                av[mt][0] = __float_as_uint(ap[0]);
                av[mt][1] = __float_as_uint(ap[8 * ASTR]);
                av[mt][2] = __float_as_uint(ap[4]);
                av[mt][3] = __float_as_uint(ap[8 * ASTR + 4]);
            }
#pragma unroll
            for (int nt = 0; nt < 4; nt++) {
                const float* bp = Bs + (kk + t) * BSTR + wn0 + nt * 8 + g;
                bv[nt][0] = __float_as_uint(bp[0]);
                bv[nt][1] = __float_as_uint(bp[4 * BSTR]);
            }
#pragma unroll
            for (int mt = 0; mt < 4; mt++)
#pragma unroll
                for (int nt = 0; nt < 4; nt++)
                    MMA_TF32(acc[mt][nt], av[mt], bv[nt]);
        }
        buf ^= 1;
    }

    // epilogue
#pragma unroll
    for (int mt = 0; mt < 4; mt++) {
#pragma unroll
        for (int nt = 0; nt < 4; nt++) {
            int row = bm0 + wm0 + mt * 16 + g;
            int col = bn0 + wn0 + nt * 8 + t * 2;
            float bb0 = bias[col], bb1 = bias[col + 1];
            float o0 = acc[mt][nt][0] + bb0;
            float o1 = acc[mt][nt][1] + bb1;
            float o2 = acc[mt][nt][2] + bb0;
            float o3 = acc[mt][nt][3] + bb1;
            if (relu) {
                o0 = fmaxf(o0, 0.f); o1 = fmaxf(o1, 0.f);
                o2 = fmaxf(o2, 0.f); o3 = fmaxf(o3, 0.f);
            }
            if (resid) {
                float2 r0 = *reinterpret_cast<const float2*>(
                    resid + (size_t)row * N + col);
                float2 r1 = *reinterpret_cast<const float2*>(
                    resid + (size_t)(row + 8) * N + col);
                o0 += r0.x; o1 += r0.y; o2 += r1.x; o3 += r1.y;
            }
            if (cvt_out) {
                o0 = f2tf32(o0); o1 = f2tf32(o1);
                o2 = f2tf32(o2); o3 = f2tf32(o3);
            }
            float2 s0 = {o0, o1}, s1 = {o2, o3};
            *reinterpret_cast<float2*>(C + (size_t)row * N + col) = s0;
            *reinterpret_cast<float2*>(C + (size_t)(row + 8) * N + col) = s1;
        }
    }
}

__global__ __launch_bounds__(256)
void tf32_gemm_kernel(int M, int N, int K, const float* __restrict__ A,
                      const float* __restrict__ B,
                      const float* __restrict__ bias,
                      const float* __restrict__ resid,
                      float* __restrict__ C, int relu, int cvt_out) {
    gemm_core(M, N, K, A, B, bias, resid, C, relu, cvt_out);
}

struct QkvPtrs {
    const float* W[3];
    const float* b[3];
    float* o[3];
};

__global__ __launch_bounds__(256)
void tf32_gemm_qkv_kernel(const float* __restrict__ A, QkvPtrs p) {
    int z = blockIdx.z;
    gemm_core(MROWS, DD, DD, A, p.W[z], p.b[z], nullptr, p.o[z], 0, 0);
}

// ---------------------------------------------------------------------------
// Flash attention: per (b, h, q-tile of 64). Bk = 64. Online softmax.
// Matches reference: scores/8 + (-1e9)(1-m); softmax; probs*m; @V; +x residual
// out written into res1 = attn + x
// ---------------------------------------------------------------------------
#define FL_SMEM_FLOATS (3*64*68 + 64*65 + 4*64)

__global__ __launch_bounds__(256)
void flash_kernel(const float* __restrict__ Q,
                  const float* __restrict__ Kg,
                  const float* __restrict__ Vg,
                  const int*   __restrict__ mask,
                  const float* __restrict__ xin,
                  float* __restrict__ out) {
    extern __shared__ float sm[];
    float* Qst = sm;                    // [d][q] stride 68
    float* Kst = Qst + 64 * 68;         // [d][k] stride 68
    float* Vs  = Kst + 64 * 68;         // [k][d] stride 68
    float* Ss  = Vs  + 64 * 68;         // [q][k] stride 65
    float* m_row = Ss + 64 * 65;
    float* l_row = m_row + 64;
    float* c_row = l_row + 64;
    float* any_row = c_row + 64;

    const int tid = threadIdx.x;
    const int qt = blockIdx.x, h = blockIdx.y, b = blockIdx.z;
    const int q0 = qt * 64;

    const float* Qgp = Q + ((size_t)(b * TT + q0) * DD + h * DH);

#pragma unroll
    for (int i = 0; i < 4; i++) {
        int lin = tid + i * 256;
        int row = lin >> 4;
        int d4 = (lin & 15) << 2;
        float4 qv = *reinterpret_cast<const float4*>(Qgp + (size_t)row * DD + d4);
        Qst[(d4 + 0) * 68 + row] = qv.x;
        Qst[(d4 + 1) * 68 + row] = qv.y;
        Qst[(d4 + 2) * 68 + row] = qv.z;
        Qst[(d4 + 3) * 68 + row] = qv.w;
    }
    if (tid < 64) {
        m_row[tid] = -INFINITY;
        l_row[tid] = 0.f;
        any_row[tid] = 0.f;
    }
    float O[16];
#pragma unroll
    for (int j = 0; j < 16; j++) O[j] = 0.f;
    __syncthreads();

    const int ty = tid >> 4, tx = tid & 15;
    const int qr0 = ty << 2, kc0 = tx << 2;
    const int qpv = tid >> 2, dg = tid & 3;
    const int db = dg << 4;

    for (int kt = 0; kt < TT / 64; kt++) {
        const int k0 = kt * 64;
        const float* Kp = Kg + ((size_t)(b * TT + k0) * DD + h * DH);
        const float* Vp = Vg + ((size_t)(b * TT + k0) * DD + h * DH);
#pragma unroll
        for (int i = 0; i < 4; i++) {
            int lin = tid + i * 256;
            int row = lin >> 4;
            int d4 = (lin & 15) << 2;
            float4 kv = *reinterpret_cast<const float4*>(Kp + (size_t)row * DD + d4);
            Kst[(d4 + 0) * 68 + row] = kv.x;
            Kst[(d4 + 1) * 68 + row] = kv.y;
            Kst[(d4 + 2) * 68 + row] = kv.z;
            Kst[(d4 + 3) * 68 + row] = kv.w;
            float4 vv = *reinterpret_cast<const float4*>(Vp + (size_t)row * DD + d4);
            *reinterpret_cast<float4*>(Vs + row * 68 + d4) = vv;
        }
        __syncthreads();

        float accS[4][4];
#pragma unroll
        for (int i = 0; i < 4; i++)
#pragma unroll
            for (int j = 0; j < 4; j++) accS[i][j] = 0.f;
#pragma unroll 8
        for (int d = 0; d < 64; d++) {
            float4 aq = *reinterpret_cast<const float4*>(Qst + d * 68 + qr0);
            float4 bk = *reinterpret_cast<const float4*>(Kst + d * 68 + kc0);
            float aa[4] = {aq.x, aq.y, aq.z, aq.w};
            float kk[4] = {bk.x, bk.y, bk.z, bk.w};
#pragma unroll
            for (int i = 0; i < 4; i++)
#pragma unroll
                for (int j = 0; j < 4; j++)
                    accS[i][j] += aa[i] * kk[j];
        }
#pragma unroll
        for (int i = 0; i < 4; i++) {
            int qg = q0 + qr0 + i;
            const int4 mv = *reinterpret_cast<const int4*>(
                mask + (size_t)b * TT * TT + (size_t)qg * TT + k0 + kc0);
            int mm[4] = {mv.x, mv.y, mv.z, mv.w};
            bool anyl = (mm[0] | mm[1] | mm[2] | mm[3]) != 0;
#pragma unroll
            for (int j = 0; j < 4; j++) {
                float s = accS[i][j] * 0.125f + (mm[j] ? 0.f : -1e9f);
                Ss[(qr0 + i) * 65 + kc0 + j] = s;
            }
            if (anyl) any_row[qr0 + i] = 1.f;
        }
        __syncthreads();

        {
            int r = tid >> 2, part = tid & 3;
            int ks = part * 16;
            float mx = -INFINITY;
#pragma unroll
            for (int k = 0; k < 16; k++) mx = fmaxf(mx, Ss[r * 65 + ks + k]);
            mx = fmaxf(mx, __shfl_xor_sync(0xffffffffu, mx, 1));
            mx = fmaxf(mx, __shfl_xor_sync(0xffffffffu, mx, 2));
            float mold = m_row[r];
            float mnew = fmaxf(mold, mx);
            float psum = 0.f;
#pragma unroll
            for (int k = 0; k < 16; k++) {
                float e = __expf(Ss[r * 65 + ks + k] - mnew);
                Ss[r * 65 + ks + k] = e;
                psum += e;
            }
            psum += __shfl_xor_sync(0xffffffffu, psum, 1);
            psum += __shfl_xor_sync(0xffffffffu, psum, 2);
            if (part == 0) {
                float c = __expf(mold - mnew);
                c_row[r] = c;
                l_row[r] = l_row[r] * c + psum;
                m_row[r] = mnew;
            }
        }
        __syncthreads();

        {
            float c = c_row[qpv];
#pragma unroll
            for (int j = 0; j < 16; j++) O[j] *= c;
#pragma unroll 8
            for (int k = 0; k < 64; k++) {
                float p = Ss[qpv * 65 + k];
                const float4* vp = reinterpret_cast<const float4*>(Vs + k * 68 + db);
                float4 v0 = vp[0], v1 = vp[1], v2 = vp[2], v3 = vp[3];
                O[0]  += p * v0.x; O[1]  += p * v0.y; O[2]  += p * v0.z; O[3]  += p * v0.w;
                O[4]  += p * v1.x; O[5]  += p * v1.y; O[6]  += p * v1.z; O[7]  += p * v1.w;
                O[8]  += p * v2.x; O[9]  += p * v2.y; O[10] += p * v2.z; O[11] += p * v2.w;
                O[12] += p * v3.x; O[13] += p * v3.y; O[14] += p * v3.z; O[15] += p * v3.w;
            }
        }
        __syncthreads();
    }

    {
        float l = l_row[qpv];
        float inv = (any_row[qpv] != 0.f) ? (1.f / l) : 0.f;
        size_t base = (size_t)(b * TT + q0 + qpv) * DD + h * DH + db;
#pragma unroll
        for (int v4 = 0; v4 < 4; v4++) {
            float4 xr = *reinterpret_cast<const float4*>(xin + base + v4 * 4);
            float4 o;
            o.x = O[v4 * 4 + 0] * inv + xr.x;
            o.y = O[v4 * 4 + 1] * inv + xr.y;
            o.z = O[v4 * 4 + 2] * inv + xr.z;
            o.w = O[v4 * 4 + 3] * inv + xr.w;
            *reinterpret_cast<float4*>(out + base + v4 * 4) = o;
        }
    }
}

// ---------------------------------------------------------------------------
// Launch
// ---------------------------------------------------------------------------
extern "C" void kernel_launch(void* const* d_in, const int* in_sizes, int n_in,
                              void* d_out, int out_size) {
    const float* x     = (const float*)d_in[0];
    const int*   mask  = (const int*)  d_in[1];
    const float* Wq    = (const float*)d_in[2];
    const float* bq    = (const float*)d_in[3];
    const float* Wk    = (const float*)d_in[4];
    const float* bk    = (const float*)d_in[5];
    const float* Wv    = (const float*)d_in[6];
    const float* bv    = (const float*)d_in[7];
    const float* g_in  = (const float*)d_in[8];
    const float* b_in  = (const float*)d_in[9];
    const float* g1    = (const float*)d_in[10];
    const float* b1    = (const float*)d_in[11];
    const float* W_ff1 = (const float*)d_in[12];
    const float* b_ff1 = (const float*)d_in[13];
    const float* W_ff2 = (const float*)d_in[14];
    const float* b_ff2 = (const float*)d_in[15];
    const float* g2    = (const float*)d_in[16];
    const float* b2    = (const float*)d_in[17];
    float* out = (float*)d_out;

    float *xn, *q, *k, *v, *res1, *h1n, *ff, *res2;
    float *wq_t, *wk_t, *wv_t, *w1_t, *w2_t;
    cudaGetSymbolAddress((void**)&xn,   g_xn);
    cudaGetSymbolAddress((void**)&q,    g_q);
    cudaGetSymbolAddress((void**)&k,    g_k);
    cudaGetSymbolAddress((void**)&v,    g_v);
    cudaGetSymbolAddress((void**)&res1, g_res1);
    cudaGetSymbolAddress((void**)&h1n,  g_h1n);
    cudaGetSymbolAddress((void**)&ff,   g_ff);
    cudaGetSymbolAddress((void**)&res2, g_res2);
    cudaGetSymbolAddress((void**)&wq_t, g_wq_t);
    cudaGetSymbolAddress((void**)&wk_t, g_wk_t);
    cudaGetSymbolAddress((void**)&wv_t, g_wv_t);
    cudaGetSymbolAddress((void**)&w1_t, g_w1_t);
    cudaGetSymbolAddress((void**)&w2_t, g_w2_t);

    const int flash_smem = FL_SMEM_FLOATS * sizeof(float);
    cudaFuncSetAttribute(flash_kernel,
                         cudaFuncAttributeMaxDynamicSharedMemorySize, flash_smem);
    cudaFuncSetAttribute(tf32_gemm_kernel,
                         cudaFuncAttributeMaxDynamicSharedMemorySize, GEMM_SMEM);
    cudaFuncSetAttribute(tf32_gemm_qkv_kernel,
                         cudaFuncAttributeMaxDynamicSharedMemorySize, GEMM_SMEM);

    // 0. weight -> tf32 copies
    {
        int n4 = DD * DD / 4;
        cvt_tf32_kernel<<<(n4 + 255) / 256, 256>>>(Wq, wq_t, n4);
        cvt_tf32_kernel<<<(n4 + 255) / 256, 256>>>(Wk, wk_t, n4);
        cvt_tf32_kernel<<<(n4 + 255) / 256, 256>>>(Wv, wv_t, n4);
        int m4 = DD * FFN / 4;
        cvt_tf32_kernel<<<(m4 + 255) / 256, 256>>>(W_ff1, w1_t, m4);
        cvt_tf32_kernel<<<(m4 + 255) / 256, 256>>>(W_ff2, w2_t, m4);
    }

    // 1. pre-LN (tf32-rounded output; consumed only by QKV GEMM)
    ln1024_kernel<<<MROWS, 256>>>(x, g_in, b_in, xn, 1);

    // 2. QKV projections (fused grid.z)
    {
        QkvPtrs p;
        p.W[0] = wq_t; p.W[1] = wk_t; p.W[2] = wv_t;
        p.b[0] = bq;   p.b[1] = bk;   p.b[2] = bv;
        p.o[0] = q;    p.o[1] = k;    p.o[2] = v;
        tf32_gemm_qkv_kernel<<<dim3(DD / BN, MROWS / BM, 3), 256, GEMM_SMEM>>>(xn, p);
    }

    // 3. attention + residual(x) -> res1
    flash_kernel<<<dim3(TT / 64, HH, BB), 256, flash_smem>>>(q, k, v, mask, x, res1);

    // 4. LN -> h1n (tf32-rounded; consumed only by FF1 GEMM)
    ln1024_kernel<<<MROWS, 256>>>(res1, g1, b1, h1n, 1);

    // 5. FF1 + relu (output tf32-rounded; consumed only by FF2 GEMM)
    tf32_gemm_kernel<<<dim3(FFN / BN, MROWS / BM), 256, GEMM_SMEM>>>(
        MROWS, FFN, DD, h1n, w1_t, b_ff1, nullptr, ff, 1, 1);

    // 6. FF2 + bias + residual(res1)
    tf32_gemm_kernel<<<dim3(DD / BN, MROWS / BM), 256, GEMM_SMEM>>>(
        MROWS, DD, FFN, ff, w2_t, b_ff2, res1, res2, 0, 0);

    // 7. final LN -> out
    ln1024_kernel<<<MROWS, 256>>>(res2, g2, b2, out, 0);
}

// round 8
// speedup vs baseline: 2.2561x; 2.2561x over previous
#include <cuda_runtime.h>
#include <cuda_bf16.h>
#include <math.h>
#include <stdint.h>

// Problem constants
#define BB 2
#define TT 2048
#define DD 1024
#define HH 16
#define DH 64
#define FFN 4096
#define MROWS (BB*TT)          // 4096
#define LN_EPS 1e-3f

// GEMM tiling
#define BM 128
#define BN 128
#define BKK 32
#define ASTR 36                 // padded stride for As [BM][ASTR]
#define BSTR 132                // padded stride for Bs [BKK][BSTR]
#define STAGE_FLOATS (BM*ASTR + BKK*BSTR)   // 4608 + 4224 = 8832
#define GEMM_SMEM (2*STAGE_FLOATS*4)        // 70656 bytes

// Flash tiling (tensor-core version)
#define QSTR 68                 // [q][d]  stride  (≡4 mod 32: A-frag conflict-free)
#define KSTR 72                 // [d][kk] stride  (≡8 mod 32: B-frag conflict-free)
#define VSTR 72                 // [kk][d] stride
#define SSTR 68                 // [q][kk] stride  (A-frag for PV)
#define FL_SMEM_FLOATS (64*QSTR + 64*KSTR + 64*VSTR + 64*SSTR + 4*64)

// ---------------------------------------------------------------------------
// Scratch (device globals; no allocation allowed)
// ---------------------------------------------------------------------------
__device__ float g_xn  [MROWS*DD];
__device__ float g_q   [MROWS*DD];
__device__ float g_k   [MROWS*DD];
__device__ float g_v   [MROWS*DD];
__device__ float g_res1[MROWS*DD];
__device__ float g_h1n [MROWS*DD];
__device__ float g_ff  [MROWS*FFN];
__device__ float g_res2[MROWS*DD];
// tf32-rounded weight copies
__device__ float g_wq_t[DD*DD];
__device__ float g_wk_t[DD*DD];
__device__ float g_wv_t[DD*DD];
__device__ float g_w1_t[DD*FFN];
__device__ float g_w2_t[FFN*DD];

// ---------------------------------------------------------------------------
// Helpers
// ---------------------------------------------------------------------------
__device__ __forceinline__ float f2tf32(float x) {
    uint32_t u;
    asm("cvt.rna.tf32.f32 %0, %1;" : "=r"(u) : "f"(x));
    return __uint_as_float(u);
}

__device__ __forceinline__ void cp16(float* dst, const float* src) {
    unsigned s = (unsigned)__cvta_generic_to_shared(dst);
    asm volatile("cp.async.cg.shared.global [%0], [%1], 16;" :: "r"(s), "l"(src));
}

#define MMA_TF32(c, a, b) \
    asm volatile("mma.sync.aligned.m16n8k8.row.col.f32.tf32.tf32.f32 " \
        "{%0,%1,%2,%3}, {%4,%5,%6,%7}, {%8,%9}, {%0,%1,%2,%3};" \
        : "+f"((c)[0]), "+f"((c)[1]), "+f"((c)[2]), "+f"((c)[3]) \
        : "r"((a)[0]), "r"((a)[1]), "r"((a)[2]), "r"((a)[3]), \
          "r"((b)[0]), "r"((b)[1]))

// ---------------------------------------------------------------------------
// Weight -> tf32 (rna) conversion, elementwise
// ---------------------------------------------------------------------------
__global__ void cvt_tf32_kernel(const float* __restrict__ in,
                                float* __restrict__ outp, int n4) {
    int i = blockIdx.x * blockDim.x + threadIdx.x;
    if (i < n4) {
        float4 v = reinterpret_cast<const float4*>(in)[i];
        v.x = f2tf32(v.x); v.y = f2tf32(v.y);
        v.z = f2tf32(v.z); v.w = f2tf32(v.w);
        reinterpret_cast<float4*>(outp)[i] = v;
    }
}

// ---------------------------------------------------------------------------
// LayerNorm over last dim (D=1024), one block of 256 threads per row.
// ---------------------------------------------------------------------------
__device__ __forceinline__ float block_reduce_sum_256(float v, float* red) {
    __syncthreads();
#pragma unroll
    for (int o = 16; o > 0; o >>= 1) v += __shfl_xor_sync(0xffffffffu, v, o);
    int lane = threadIdx.x & 31, wid = threadIdx.x >> 5;
    if (lane == 0) red[wid] = v;
    __syncthreads();
    if (wid == 0) {
        v = (lane < 8) ? red[lane] : 0.f;
#pragma unroll
        for (int o = 4; o > 0; o >>= 1) v += __shfl_xor_sync(0xffffffffu, v, o);
        if (lane == 0) red[0] = v;
    }
    __syncthreads();
    return red[0];
}

__global__ void ln1024_kernel(const float* __restrict__ x,
                              const float* __restrict__ gamma,
                              const float* __restrict__ beta,
                              float* __restrict__ out,
                              int tf32out) {
    __shared__ float red[8];
    int row = blockIdx.x;
    int t = threadIdx.x;
    const float4 v = reinterpret_cast<const float4*>(x + (size_t)row * DD)[t];

    float s = v.x + v.y + v.z + v.w;
    float mu = block_reduce_sum_256(s, red) * (1.0f / DD);

    float dx = v.x - mu, dy = v.y - mu, dz = v.z - mu, dw = v.w - mu;
    float q = dx*dx + dy*dy + dz*dz + dw*dw;
    float var = block_reduce_sum_256(q, red) * (1.0f / DD);
    float r = rsqrtf(var + LN_EPS);

    const float4 gg = reinterpret_cast<const float4*>(gamma)[t];
    const float4 bb = reinterpret_cast<const float4*>(beta)[t];
    float4 o;
    o.x = dx * r * gg.x + bb.x;
    o.y = dy * r * gg.y + bb.y;
    o.z = dz * r * gg.z + bb.z;
    o.w = dw * r * gg.w + bb.w;
    if (tf32out) {
        o.x = f2tf32(o.x); o.y = f2tf32(o.y);
        o.z = f2tf32(o.z); o.w = f2tf32(o.w);
    }
    reinterpret_cast<float4*>(out + (size_t)row * DD)[t] = o;
}

// ---------------------------------------------------------------------------
// TF32 tensor-core GEMM core (unchanged from round 6)
// ---------------------------------------------------------------------------
__device__ __forceinline__ void gemm_prefetch(const float* __restrict__ A,
                                              const float* __restrict__ B,
                                              int K, int N, int bm0, int bn0,
                                              int kt, float* As, float* Bs,
                                              int tid) {
#pragma unroll
    for (int i = 0; i < 4; i++) {
        int lin = tid + i * 256;
        int row = lin >> 3, c4 = (lin & 7) << 2;
        cp16(As + row * ASTR + c4,
             A + (size_t)(bm0 + row) * K + (size_t)kt * BKK + c4);
    }
#pragma unroll
    for (int i = 0; i < 4; i++) {
        int lin = tid + i * 256;
        int k = lin >> 5, n4 = (lin & 31) << 2;
        cp16(Bs + k * BSTR + n4,
             B + (size_t)(kt * BKK + k) * N + bn0 + n4);
    }
}

__device__ __forceinline__ void gemm_core(int M, int N, int K,
    const float* __restrict__ A, const float* __restrict__ B,
    const float* __restrict__ bias, const float* __restrict__ resid,
    float* __restrict__ C, int relu, int cvt_out) {
    extern __shared__ float sm[];
    const int tid = threadIdx.x;
    const int warp = tid >> 5, lane = tid & 31;
    const int g = lane >> 2, t = lane & 3;
    const int wm0 = (warp & 1) << 6;
    const int wn0 = (warp >> 1) << 5;
    const int bm0 = blockIdx.y * BM, bn0 = blockIdx.x * BN;

    float acc[4][4][4];
#pragma unroll
    for (int i = 0; i < 4; i++)
#pragma unroll
        for (int j = 0; j < 4; j++)
#pragma unroll
            for (int r = 0; r < 4; r++) acc[i][j][r] = 0.f;

    const int nkt = K / BKK;
    gemm_prefetch(A, B, K, N, bm0, bn0, 0, sm, sm + BM * ASTR, tid);
    asm volatile("cp.async.commit_group;");

    int buf = 0;
    for (int kt = 0; kt < nkt; kt++) {
        asm volatile("cp.async.wait_group 0;");
        __syncthreads();
        if (kt + 1 < nkt) {
            float* As_n = sm + (buf ^ 1) * STAGE_FLOATS;
            gemm_prefetch(A, B, K, N, bm0, bn0, kt + 1, As_n,
                          As_n + BM * ASTR, tid);
            asm volatile("cp.async.commit_group;");
        }
        const float* As = sm + buf * STAGE_FLOATS;
        const float* Bs = As + BM * ASTR;
#pragma unroll
        for (int ks = 0; ks < 4; ks++) {
            const int kk = ks * 8;
            unsigned av[4][4], bv[4][2];
#pragma unroll
            for (int mt = 0; mt < 4; mt++) {
                const float* ap = As + (wm0 + mt * 16 + g) * ASTR + kk + t;
                av[mt][0] = __float_as_uint(ap[0]);
                av[mt][1] = __float_as_uint(ap[8 * ASTR]);
                av[mt][2] = __float_as_uint(ap[4]);
                av[mt][3] = __float_as_uint(ap[8 * ASTR + 4]);
            }
#pragma unroll
            for (int nt = 0; nt < 4; nt++) {
                const float* bp = Bs + (kk + t) * BSTR + wn0 + nt * 8 + g;
                bv[nt][0] = __float_as_uint(bp[0]);
                bv[nt][1] = __float_as_uint(bp[4 * BSTR]);
            }
#pragma unroll
            for (int mt = 0; mt < 4; mt++)
#pragma unroll
                for (int nt = 0; nt < 4; nt++)
                    MMA_TF32(acc[mt][nt], av[mt], bv[nt]);
        }
        buf ^= 1;
    }

#pragma unroll
    for (int mt = 0; mt < 4; mt++) {
#pragma unroll
        for (int nt = 0; nt < 4; nt++) {
            int row = bm0 + wm0 + mt * 16 + g;
            int col = bn0 + wn0 + nt * 8 + t * 2;
            float bb0 = bias[col], bb1 = bias[col + 1];
            float o0 = acc[mt][nt][0] + bb0;
            float o1 = acc[mt][nt][1] + bb1;
            float o2 = acc[mt][nt][2] + bb0;
            float o3 = acc[mt][nt][3] + bb1;
            if (relu) {
                o0 = fmaxf(o0, 0.f); o1 = fmaxf(o1, 0.f);
                o2 = fmaxf(o2, 0.f); o3 = fmaxf(o3, 0.f);
            }
            if (resid) {
                float2 r0 = *reinterpret_cast<const float2*>(
                    resid + (size_t)row * N + col);
                float2 r1 = *reinterpret_cast<const float2*>(
                    resid + (size_t)(row + 8) * N + col);
                o0 += r0.x; o1 += r0.y; o2 += r1.x; o3 += r1.y;
            }
            if (cvt_out) {
                o0 = f2tf32(o0); o1 = f2tf32(o1);
                o2 = f2tf32(o2); o3 = f2tf32(o3);
            }
            float2 s0 = {o0, o1}, s1 = {o2, o3};
            *reinterpret_cast<float2*>(C + (size_t)row * N + col) = s0;
            *reinterpret_cast<float2*>(C + (size_t)(row + 8) * N + col) = s1;
        }
    }
}

__global__ __launch_bounds__(256)
void tf32_gemm_kernel(int M, int N, int K, const float* __restrict__ A,
                      const float* __restrict__ B,
                      const float* __restrict__ bias,
                      const float* __restrict__ resid,
                      float* __restrict__ C, int relu, int cvt_out) {
    gemm_core(M, N, K, A, B, bias, resid, C, relu, cvt_out);
}

struct QkvPtrs {
    const float* W[3];
    const float* b[3];
    float* o[3];
};

__global__ __launch_bounds__(256)
void tf32_gemm_qkv_kernel(const float* __restrict__ A, QkvPtrs p) {
    int z = blockIdx.z;
    // cvt_out=1: q/k/v feed the tensor-core flash kernel (tf32 operands)
    gemm_core(MROWS, DD, DD, A, p.W[z], p.b[z], nullptr, p.o[z], 0, 1);
}

// ---------------------------------------------------------------------------
// Flash attention, TENSOR-CORE version.
// Per CTA: (b, h, 64 q-rows). k-tiles of 64. 8 warps.
// Warp w owns rows wm=(w&3)*16, cols wn=(w>>2)*32 of the 64x64 S / O tiles.
// Q,K,V arrive tf32-pre-rounded (QKV GEMM epilogue). P stored tf32-rounded.
// ---------------------------------------------------------------------------
__global__ __launch_bounds__(256)
void flash_tc_kernel(const float* __restrict__ Q,
                     const float* __restrict__ Kg,
                     const float* __restrict__ Vg,
                     const int*   __restrict__ mask,
                     const float* __restrict__ xin,
                     float* __restrict__ out) {
    extern __shared__ float sm[];
    float* Qs  = sm;                    // [q][d]   stride QSTR
    float* Kst = Qs  + 64 * QSTR;       // [d][kk]  stride KSTR (K transposed)
    float* Vs  = Kst + 64 * KSTR;       // [kk][d]  stride VSTR
    float* Ss  = Vs  + 64 * VSTR;       // [q][kk]  stride SSTR (S then P)
    float* m_row   = Ss + 64 * SSTR;
    float* l_row   = m_row + 64;
    float* c_row   = l_row + 64;
    float* any_row = c_row + 64;

    const int tid = threadIdx.x;
    const int warp = tid >> 5, lane = tid & 31;
    const int g = lane >> 2, t = lane & 3;
    const int wm = (warp & 3) << 4;     // 0,16,32,48
    const int wn = (warp >> 2) << 5;    // 0,32
    const int qt = blockIdx.x, h = blockIdx.y, b = blockIdx.z;
    const int q0 = qt * 64;

    // load Q tile [q][d] row-major
    const float* Qgp = Q + ((size_t)(b * TT + q0) * DD + h * DH);
#pragma unroll
    for (int i = 0; i < 4; i++) {
        int lin = tid + i * 256;
        int row = lin >> 4;
        int d4 = (lin & 15) << 2;
        float4 qv = *reinterpret_cast<const float4*>(Qgp + (size_t)row * DD + d4);
        *reinterpret_cast<float4*>(Qs + row * QSTR + d4) = qv;
    }
    if (tid < 64) {
        m_row[tid] = -INFINITY;
        l_row[tid] = 0.f;
        any_row[tid] = 0.f;
    }
    float oacc[4][4];
#pragma unroll
    for (int nt = 0; nt < 4; nt++)
#pragma unroll
        for (int r = 0; r < 4; r++) oacc[nt][r] = 0.f;
    __syncthreads();

    for (int kt = 0; kt < TT / 64; kt++) {
        const int k0 = kt * 64;
        const float* Kp = Kg + ((size_t)(b * TT + k0) * DD + h * DH);
        const float* Vp = Vg + ((size_t)(b * TT + k0) * DD + h * DH);
        // K transposed into [d][kk]; V natural [kk][d]
#pragma unroll
        for (int i = 0; i < 4; i++) {
            int lin = tid + i * 256;
            int row = lin >> 4;
            int d4 = (lin & 15) << 2;
            float4 kv = *reinterpret_cast<const float4*>(Kp + (size_t)row * DD + d4);
            Kst[(d4 + 0) * KSTR + row] = kv.x;
            Kst[(d4 + 1) * KSTR + row] = kv.y;
            Kst[(d4 + 2) * KSTR + row] = kv.z;
            Kst[(d4 + 3) * KSTR + row] = kv.w;
            float4 vv = *reinterpret_cast<const float4*>(Vp + (size_t)row * DD + d4);
            *reinterpret_cast<float4*>(Vs + row * VSTR + d4) = vv;
        }
        __syncthreads();

        // ---- S = Q K^T via tensor cores ----
        float sacc[4][4];
#pragma unroll
        for (int nt = 0; nt < 4; nt++)
#pragma unroll
            for (int r = 0; r < 4; r++) sacc[nt][r] = 0.f;
#pragma unroll
        for (int ks = 0; ks < 8; ks++) {
            const int kk = ks * 8;
            unsigned a[4];
            const float* ap = Qs + (wm + g) * QSTR + kk + t;
            a[0] = __float_as_uint(ap[0]);
            a[1] = __float_as_uint(ap[8 * QSTR]);
            a[2] = __float_as_uint(ap[4]);
            a[3] = __float_as_uint(ap[8 * QSTR + 4]);
#pragma unroll
            for (int nt = 0; nt < 4; nt++) {
                unsigned bv2[2];
                const float* bp = Kst + (kk + t) * KSTR + wn + nt * 8 + g;
                bv2[0] = __float_as_uint(bp[0]);
                bv2[1] = __float_as_uint(bp[4 * KSTR]);
                MMA_TF32(sacc[nt], a, bv2);
            }
        }
        // write scaled S to smem
#pragma unroll
        for (int nt = 0; nt < 4; nt++) {
            int col = wn + nt * 8 + 2 * t;
            float2 s0 = {sacc[nt][0] * 0.125f, sacc[nt][1] * 0.125f};
            float2 s1 = {sacc[nt][2] * 0.125f, sacc[nt][3] * 0.125f};
            *reinterpret_cast<float2*>(Ss + (wm + g) * SSTR + col) = s0;
            *reinterpret_cast<float2*>(Ss + (wm + g + 8) * SSTR + col) = s1;
        }
        __syncthreads();

        // ---- online softmax (4 threads per row) ----
        {
            int r = tid >> 2, part = tid & 3;
            int ks0 = part * 16;
            const int4* mp = reinterpret_cast<const int4*>(
                mask + (size_t)b * TT * TT + (size_t)(q0 + r) * TT + k0 + ks0);
            int4 m0 = mp[0], m1 = mp[1], m2 = mp[2], m3 = mp[3];
            int mm[16] = {m0.x, m0.y, m0.z, m0.w, m1.x, m1.y, m1.z, m1.w,
                          m2.x, m2.y, m2.z, m2.w, m3.x, m3.y, m3.z, m3.w};
            float sv[16];
            float mx = -INFINITY;
            int anyl = 0;
#pragma unroll
            for (int k = 0; k < 16; k++) {
                float s = Ss[r * SSTR + ks0 + k] + (mm[k] ? 0.f : -1e9f);
                sv[k] = s;
                mx = fmaxf(mx, s);
                anyl |= mm[k];
            }
            mx = fmaxf(mx, __shfl_xor_sync(0xffffffffu, mx, 1));
            mx = fmaxf(mx, __shfl_xor_sync(0xffffffffu, mx, 2));
            float mold = m_row[r];
            float mnew = fmaxf(mold, mx);
            float psum = 0.f;
#pragma unroll
            for (int k = 0; k < 16; k++) {
                float e = __expf(sv[k] - mnew);
                Ss[r * SSTR + ks0 + k] = f2tf32(e);   // P, pre-rounded for mma
                psum += e;
            }
            psum += __shfl_xor_sync(0xffffffffu, psum, 1);
            psum += __shfl_xor_sync(0xffffffffu, psum, 2);
            if (anyl) any_row[r] = 1.f;               // benign race: all store 1
            if (part == 0) {
                float c = __expf(mold - mnew);        // 0 on first tile
                c_row[r] = c;
                l_row[r] = l_row[r] * c + psum;
                m_row[r] = mnew;
            }
        }
        __syncthreads();

        // ---- O = O*c + P @ V via tensor cores ----
        {
            float c0 = c_row[wm + g];
            float c1 = c_row[wm + g + 8];
#pragma unroll
            for (int nt = 0; nt < 4; nt++) {
                oacc[nt][0] *= c0; oacc[nt][1] *= c0;
                oacc[nt][2] *= c1; oacc[nt][3] *= c1;
            }
#pragma unroll
            for (int ks = 0; ks < 8; ks++) {
                const int kk = ks * 8;
                unsigned a[4];
                const float* ap = Ss + (wm + g) * SSTR + kk + t;
                a[0] = __float_as_uint(ap[0]);
                a[1] = __float_as_uint(ap[8 * SSTR]);
                a[2] = __float_as_uint(ap[4]);
                a[3] = __float_as_uint(ap[8 * SSTR + 4]);
#pragma unroll
                for (int nt = 0; nt < 4; nt++) {
                    unsigned bv2[2];
                    const float* bp = Vs + (kk + t) * VSTR + wn + nt * 8 + g;
                    bv2[0] = __float_as_uint(bp[0]);
                    bv2[1] = __float_as_uint(bp[4 * VSTR]);
                    MMA_TF32(oacc[nt], a, bv2);
                }
            }
        }
        __syncthreads();  // protect Kst/Vs/Ss before next tile's loads
    }

    // ---- epilogue: normalize, zero fully-masked rows, add residual x ----
    {
        int r0 = wm + g, r1 = wm + g + 8;
        float inv0 = (any_row[r0] != 0.f) ? (1.f / l_row[r0]) : 0.f;
        float inv1 = (any_row[r1] != 0.f) ? (1.f / l_row[r1]) : 0.f;
#pragma unroll
        for (int nt = 0; nt < 4; nt++) {
            int col = h * DH + wn + nt * 8 + 2 * t;
            size_t base0 = (size_t)(b * TT + q0 + r0) * DD + col;
            size_t base1 = (size_t)(b * TT + q0 + r1) * DD + col;
            float2 x0 = *reinterpret_cast<const float2*>(xin + base0);
            float2 x1 = *reinterpret_cast<const float2*>(xin + base1);
            float2 o0 = {oacc[nt][0] * inv0 + x0.x, oacc[nt][1] * inv0 + x0.y};
            float2 o1 = {oacc[nt][2] * inv1 + x1.x, oacc[nt][3] * inv1 + x1.y};
            *reinterpret_cast<float2*>(out + base0) = o0;
            *reinterpret_cast<float2*>(out + base1) = o1;
        }
    }
}

// ---------------------------------------------------------------------------
// Launch
// ---------------------------------------------------------------------------
extern "C" void kernel_launch(void* const* d_in, const int* in_sizes, int n_in,
                              void* d_out, int out_size) {
    const float* x     = (const float*)d_in[0];
    const int*   mask  = (const int*)  d_in[1];
    const float* Wq    = (const float*)d_in[2];
    const float* bq    = (const float*)d_in[3];
    const float* Wk    = (const float*)d_in[4];
    const float* bk    = (const float*)d_in[5];
    const float* Wv    = (const float*)d_in[6];
    const float* bv    = (const float*)d_in[7];
    const float* g_in  = (const float*)d_in[8];
    const float* b_in  = (const float*)d_in[9];
    const float* g1    = (const float*)d_in[10];
    const float* b1    = (const float*)d_in[11];
    const float* W_ff1 = (const float*)d_in[12];
    const float* b_ff1 = (const float*)d_in[13];
    const float* W_ff2 = (const float*)d_in[14];
    const float* b_ff2 = (const float*)d_in[15];
    const float* g2    = (const float*)d_in[16];
    const float* b2    = (const float*)d_in[17];
    float* out = (float*)d_out;

    float *xn, *q, *k, *v, *res1, *h1n, *ff, *res2;
    float *wq_t, *wk_t, *wv_t, *w1_t, *w2_t;
    cudaGetSymbolAddress((void**)&xn,   g_xn);
    cudaGetSymbolAddress((void**)&q,    g_q);
    cudaGetSymbolAddress((void**)&k,    g_k);
    cudaGetSymbolAddress((void**)&v,    g_v);
    cudaGetSymbolAddress((void**)&res1, g_res1);
    cudaGetSymbolAddress((void**)&h1n,  g_h1n);
    cudaGetSymbolAddress((void**)&ff,   g_ff);
    cudaGetSymbolAddress((void**)&res2, g_res2);
    cudaGetSymbolAddress((void**)&wq_t, g_wq_t);
    cudaGetSymbolAddress((void**)&wk_t, g_wk_t);
    cudaGetSymbolAddress((void**)&wv_t, g_wv_t);
    cudaGetSymbolAddress((void**)&w1_t, g_w1_t);
    cudaGetSymbolAddress((void**)&w2_t, g_w2_t);

    const int flash_smem = FL_SMEM_FLOATS * sizeof(float);
    cudaFuncSetAttribute(flash_tc_kernel,
                         cudaFuncAttributeMaxDynamicSharedMemorySize, flash_smem);
    cudaFuncSetAttribute(tf32_gemm_kernel,
                         cudaFuncAttributeMaxDynamicSharedMemorySize, GEMM_SMEM);
    cudaFuncSetAttribute(tf32_gemm_qkv_kernel,
                         cudaFuncAttributeMaxDynamicSharedMemorySize, GEMM_SMEM);

    // 0. weight -> tf32 copies
    {
        int n4 = DD * DD / 4;
        cvt_tf32_kernel<<<(n4 + 255) / 256, 256>>>(Wq, wq_t, n4);
        cvt_tf32_kernel<<<(n4 + 255) / 256, 256>>>(Wk, wk_t, n4);
        cvt_tf32_kernel<<<(n4 + 255) / 256, 256>>>(Wv, wv_t, n4);
        int m4 = DD * FFN / 4;
        cvt_tf32_kernel<<<(m4 + 255) / 256, 256>>>(W_ff1, w1_t, m4);
        cvt_tf32_kernel<<<(m4 + 255) / 256, 256>>>(W_ff2, w2_t, m4);
    }

    // 1. pre-LN (tf32-rounded output; consumed only by QKV GEMM)
    ln1024_kernel<<<MROWS, 256>>>(x, g_in, b_in, xn, 1);

    // 2. QKV projections (fused grid.z; outputs tf32-rounded for flash mma)
    {
        QkvPtrs p;
        p.W[0] = wq_t; p.W[1] = wk_t; p.W[2] = wv_t;
        p.b[0] = bq;   p.b[1] = bk;   p.b[2] = bv;
        p.o[0] = q;    p.o[1] = k;    p.o[2] = v;
        tf32_gemm_qkv_kernel<<<dim3(DD / BN, MROWS / BM, 3), 256, GEMM_SMEM>>>(xn, p);
    }

    // 3. attention + residual(x) -> res1  (tensor-core flash)
    flash_tc_kernel<<<dim3(TT / 64, HH, BB), 256, flash_smem>>>(q, k, v, mask, x, res1);

    // 4. LN -> h1n (tf32-rounded; consumed only by FF1 GEMM)
    ln1024_kernel<<<MROWS, 256>>>(res1, g1, b1, h1n, 1);

    // 5. FF1 + relu (output tf32-rounded; consumed only by FF2 GEMM)
    tf32_gemm_kernel<<<dim3(FFN / BN, MROWS / BM), 256, GEMM_SMEM>>>(
        MROWS, FFN, DD, h1n, w1_t, b_ff1, nullptr, ff, 1, 1);

    // 6. FF2 + bias + residual(res1)
    tf32_gemm_kernel<<<dim3(DD / BN, MROWS / BM), 256, GEMM_SMEM>>>(
        MROWS, DD, FFN, ff, w2_t, b_ff2, res1, res2, 0, 0);

    // 7. final LN -> out
    ln1024_kernel<<<MROWS, 256>>>(res2, g2, b2, out, 0);
}

// round 9
// speedup vs baseline: 2.8712x; 1.2727x over previous
#include <cuda_runtime.h>
#include <cuda_bf16.h>
#include <math.h>
#include <stdint.h>

// Problem constants
#define BB 2
#define TT 2048
#define DD 1024
#define HH 16
#define DH 64
#define FFN 4096
#define MROWS (BB*TT)          // 4096
#define LN_EPS 1e-3f

// GEMM tiling: 128x128x32 block, 128 threads (4 warps), warp tile 64x64
#define BM 128
#define BN 128
#define BKK 32
#define ASTR 36                 // ≡4 mod 32: A-frag banks 4g+t all distinct
#define BSTR 136                // ≡8 mod 32: B-frag banks 8t+g all distinct
#define STAGE_FLOATS (BM*ASTR + BKK*BSTR)   // 4608 + 4352 = 8960
#define GEMM_SMEM (2*STAGE_FLOATS*4)        // 71680 bytes

// Flash tiling
#define QSTR 68                 // [q][d]
#define KSTR 72                 // [d][kk] (≡8 mod 32: B-frag conflict-free)
#define VSTR 72                 // [kk][d]
#define SSTR 68                 // [q][kk]
#define FL_SMEM_FLOATS (64*QSTR + 2*64*KSTR + 2*64*VSTR + 64*SSTR + 4*64)

// ---------------------------------------------------------------------------
// Scratch (device globals; no allocation allowed)
// ---------------------------------------------------------------------------
__device__ float g_xn  [MROWS*DD];
__device__ float g_q   [MROWS*DD];
__device__ float g_k   [MROWS*DD];
__device__ float g_kT  [MROWS*DD];   // [(b*HH+h)*DH + d][t]
__device__ float g_v   [MROWS*DD];
__device__ float g_res1[MROWS*DD];
__device__ float g_h1n [MROWS*DD];
__device__ float g_ff  [MROWS*FFN];
__device__ float g_res2[MROWS*DD];
// tf32-rounded weight copies
__device__ float g_wq_t[DD*DD];
__device__ float g_wk_t[DD*DD];
__device__ float g_wv_t[DD*DD];
__device__ float g_w1_t[DD*FFN];
__device__ float g_w2_t[FFN*DD];

// ---------------------------------------------------------------------------
// Helpers
// ---------------------------------------------------------------------------
__device__ __forceinline__ float f2tf32(float x) {
    uint32_t u;
    asm("cvt.rna.tf32.f32 %0, %1;" : "=r"(u) : "f"(x));
    return __uint_as_float(u);
}

__device__ __forceinline__ void cp16(float* dst, const float* src) {
    unsigned s = (unsigned)__cvta_generic_to_shared(dst);
    asm volatile("cp.async.cg.shared.global [%0], [%1], 16;" :: "r"(s), "l"(src));
}

#define MMA_TF32(c, a, b) \
    asm volatile("mma.sync.aligned.m16n8k8.row.col.f32.tf32.tf32.f32 " \
        "{%0,%1,%2,%3}, {%4,%5,%6,%7}, {%8,%9}, {%0,%1,%2,%3};" \
        : "+f"((c)[0]), "+f"((c)[1]), "+f"((c)[2]), "+f"((c)[3]) \
        : "r"((a)[0]), "r"((a)[1]), "r"((a)[2]), "r"((a)[3]), \
          "r"((b)[0]), "r"((b)[1]))

// ---------------------------------------------------------------------------
// Weight -> tf32 (rna) conversion; 3 arrays per launch via grid.z
// ---------------------------------------------------------------------------
struct CvtJobs {
    const float* in[3];
    float* out[3];
};

__global__ void cvt_tf32_multi_kernel(CvtJobs j, int n4) {
    int i = blockIdx.x * blockDim.x + threadIdx.x;
    int z = blockIdx.z;
    if (i < n4 && j.in[z]) {
        float4 v = reinterpret_cast<const float4*>(j.in[z])[i];
        v.x = f2tf32(v.x); v.y = f2tf32(v.y);
        v.z = f2tf32(v.z); v.w = f2tf32(v.w);
        reinterpret_cast<float4*>(j.out[z])[i] = v;
    }
}

// ---------------------------------------------------------------------------
// K transpose: k[b*TT+t][h*DH+d] -> kT[(b*HH+h)*DH+d][t]
// ---------------------------------------------------------------------------
__global__ void transpose_k_kernel(const float* __restrict__ k,
                                   float* __restrict__ kT) {
    __shared__ float tile[32][33];
    int t0 = blockIdx.x * 32, d0 = blockIdx.y * 32, b = blockIdx.z;
    int tx = threadIdx.x, ty = threadIdx.y;    // 32 x 8
#pragma unroll
    for (int j = 0; j < 4; j++)
        tile[ty + 8 * j][tx] = k[(size_t)(b * TT + t0 + ty + 8 * j) * DD + d0 + tx];
    __syncthreads();
#pragma unroll
    for (int j = 0; j < 4; j++)
        kT[(size_t)(b * DD + d0 + ty + 8 * j) * TT + t0 + tx] = tile[tx][ty + 8 * j];
}

// ---------------------------------------------------------------------------
// LayerNorm over last dim (D=1024), one block of 256 threads per row.
// ---------------------------------------------------------------------------
__device__ __forceinline__ float block_reduce_sum_256(float v, float* red) {
    __syncthreads();
#pragma unroll
    for (int o = 16; o > 0; o >>= 1) v += __shfl_xor_sync(0xffffffffu, v, o);
    int lane = threadIdx.x & 31, wid = threadIdx.x >> 5;
    if (lane == 0) red[wid] = v;
    __syncthreads();
    if (wid == 0) {
        v = (lane < 8) ? red[lane] : 0.f;
#pragma unroll
        for (int o = 4; o > 0; o >>= 1) v += __shfl_xor_sync(0xffffffffu, v, o);
        if (lane == 0) red[0] = v;
    }
    __syncthreads();
    return red[0];
}

__global__ void ln1024_kernel(const float* __restrict__ x,
                              const float* __restrict__ gamma,
                              const float* __restrict__ beta,
                              float* __restrict__ out,
                              int tf32out) {
    __shared__ float red[8];
    int row = blockIdx.x;
    int t = threadIdx.x;
    const float4 v = reinterpret_cast<const float4*>(x + (size_t)row * DD)[t];

    float s = v.x + v.y + v.z + v.w;
    float mu = block_reduce_sum_256(s, red) * (1.0f / DD);

    float dx = v.x - mu, dy = v.y - mu, dz = v.z - mu, dw = v.w - mu;
    float q = dx*dx + dy*dy + dz*dz + dw*dw;
    float var = block_reduce_sum_256(q, red) * (1.0f / DD);
    float r = rsqrtf(var + LN_EPS);

    const float4 gg = reinterpret_cast<const float4*>(gamma)[t];
    const float4 bb = reinterpret_cast<const float4*>(beta)[t];
    float4 o;
    o.x = dx * r * gg.x + bb.x;
    o.y = dy * r * gg.y + bb.y;
    o.z = dz * r * gg.z + bb.z;
    o.w = dw * r * gg.w + bb.w;
    if (tf32out) {
        o.x = f2tf32(o.x); o.y = f2tf32(o.y);
        o.z = f2tf32(o.z); o.w = f2tf32(o.w);
    }
    reinterpret_cast<float4*>(out + (size_t)row * DD)[t] = o;
}

// ---------------------------------------------------------------------------
// TF32 tensor-core GEMM core: 128 threads, 4 warps, warp tile 64x64.
// C[M,N] = A[M,K] @ B[K,N] + bias (+relu) (+resid) (+cvt_out)
// ---------------------------------------------------------------------------
__device__ __forceinline__ void gemm_prefetch(const float* __restrict__ A,
                                              const float* __restrict__ B,
                                              int K, int N, int bm0, int bn0,
                                              int kt, float* As, float* Bs,
                                              int tid) {
#pragma unroll
    for (int i = 0; i < 8; i++) {
        int lin = tid + i * 128;               // 0..1023
        int row = lin >> 3, c4 = (lin & 7) << 2;
        cp16(As + row * ASTR + c4,
             A + (size_t)(bm0 + row) * K + (size_t)kt * BKK + c4);
    }
#pragma unroll
    for (int i = 0; i < 8; i++) {
        int lin = tid + i * 128;
        int k = lin >> 5, n4 = (lin & 31) << 2;
        cp16(Bs + k * BSTR + n4,
             B + (size_t)(kt * BKK + k) * N + bn0 + n4);
    }
}

__device__ __forceinline__ void gemm_core(int M, int N, int K,
    const float* __restrict__ A, const float* __restrict__ B,
    const float* __restrict__ bias, const float* __restrict__ resid,
    float* __restrict__ C, int relu, int cvt_out) {
    extern __shared__ float sm[];
    const int tid = threadIdx.x;
    const int warp = tid >> 5, lane = tid & 31;
    const int g = lane >> 2, t = lane & 3;
    const int wm0 = (warp & 1) << 6;           // 0 or 64
    const int wn0 = (warp >> 1) << 6;          // 0 or 64
    const int bm0 = blockIdx.y * BM, bn0 = blockIdx.x * BN;

    float acc[4][8][4];
#pragma unroll
    for (int i = 0; i < 4; i++)
#pragma unroll
        for (int j = 0; j < 8; j++)
#pragma unroll
            for (int r = 0; r < 4; r++) acc[i][j][r] = 0.f;

    const int nkt = K / BKK;
    gemm_prefetch(A, B, K, N, bm0, bn0, 0, sm, sm + BM * ASTR, tid);
    asm volatile("cp.async.commit_group;");

    int buf = 0;
    for (int kt = 0; kt < nkt; kt++) {
        asm volatile("cp.async.wait_group 0;");
        __syncthreads();
        if (kt + 1 < nkt) {
            float* As_n = sm + (buf ^ 1) * STAGE_FLOATS;
            gemm_prefetch(A, B, K, N, bm0, bn0, kt + 1, As_n,
                          As_n + BM * ASTR, tid);
            asm volatile("cp.async.commit_group;");
        }
        const float* As = sm + buf * STAGE_FLOATS;
        const float* Bs = As + BM * ASTR;
#pragma unroll
        for (int ks = 0; ks < 4; ks++) {
            const int kk = ks * 8;
            unsigned av[4][4], bv[8][2];
#pragma unroll
            for (int mt = 0; mt < 4; mt++) {
                const float* ap = As + (wm0 + mt * 16 + g) * ASTR + kk + t;
                av[mt][0] = __float_as_uint(ap[0]);
                av[mt][1] = __float_as_uint(ap[8 * ASTR]);
                av[mt][2] = __float_as_uint(ap[4]);
                av[mt][3] = __float_as_uint(ap[8 * ASTR + 4]);
            }
#pragma unroll
            for (int nt = 0; nt < 8; nt++) {
                const float* bp = Bs + (kk + t) * BSTR + wn0 + nt * 8 + g;
                bv[nt][0] = __float_as_uint(bp[0]);
                bv[nt][1] = __float_as_uint(bp[4 * BSTR]);
            }
#pragma unroll
            for (int mt = 0; mt < 4; mt++)
#pragma unroll
                for (int nt = 0; nt < 8; nt++)
                    MMA_TF32(acc[mt][nt], av[mt], bv[nt]);
        }
        buf ^= 1;
    }

#pragma unroll
    for (int mt = 0; mt < 4; mt++) {
#pragma unroll
        for (int nt = 0; nt < 8; nt++) {
            int row = bm0 + wm0 + mt * 16 + g;
            int col = bn0 + wn0 + nt * 8 + t * 2;
            float bb0 = bias[col], bb1 = bias[col + 1];
            float o0 = acc[mt][nt][0] + bb0;
            float o1 = acc[mt][nt][1] + bb1;
            float o2 = acc[mt][nt][2] + bb0;
            float o3 = acc[mt][nt][3] + bb1;
            if (relu) {
                o0 = fmaxf(o0, 0.f); o1 = fmaxf(o1, 0.f);
                o2 = fmaxf(o2, 0.f); o3 = fmaxf(o3, 0.f);
            }
            if (resid) {
                float2 r0 = *reinterpret_cast<const float2*>(
                    resid + (size_t)row * N + col);
                float2 r1 = *reinterpret_cast<const float2*>(
                    resid + (size_t)(row + 8) * N + col);
                o0 += r0.x; o1 += r0.y; o2 += r1.x; o3 += r1.y;
            }
            if (cvt_out) {
                o0 = f2tf32(o0); o1 = f2tf32(o1);
                o2 = f2tf32(o2); o3 = f2tf32(o3);
            }
            float2 s0 = {o0, o1}, s1 = {o2, o3};
            *reinterpret_cast<float2*>(C + (size_t)row * N + col) = s0;
            *reinterpret_cast<float2*>(C + (size_t)(row + 8) * N + col) = s1;
        }
    }
}

__global__ __launch_bounds__(128)
void tf32_gemm_kernel(int M, int N, int K, const float* __restrict__ A,
                      const float* __restrict__ B,
                      const float* __restrict__ bias,
                      const float* __restrict__ resid,
                      float* __restrict__ C, int relu, int cvt_out) {
    gemm_core(M, N, K, A, B, bias, resid, C, relu, cvt_out);
}

struct QkvPtrs {
    const float* W[3];
    const float* b[3];
    float* o[3];
};

__global__ __launch_bounds__(128)
void tf32_gemm_qkv_kernel(const float* __restrict__ A, QkvPtrs p) {
    int z = blockIdx.z;
    gemm_core(MROWS, DD, DD, A, p.W[z], p.b[z], nullptr, p.o[z], 0, 1);
}

// ---------------------------------------------------------------------------
// Flash attention (tensor cores) with cp.async double-buffered K/V.
// Per CTA: (b, h, 64 q-rows). k-tiles of 64. 8 warps, warp tile 16x32 of S/O.
// K comes from kT [(b*HH+h)*DH+d][t] so tiles are contiguous per d-row.
// ---------------------------------------------------------------------------
__device__ __forceinline__ void fl_prefetch_kv(const float* __restrict__ kTp,
                                               const float* __restrict__ Vp,
                                               float* Kst, float* Vs, int tid) {
#pragma unroll
    for (int i = 0; i < 4; i++) {
        int lin = tid + i * 256;           // 0..1023
        int row = lin >> 4, c4 = (lin & 15) << 2;
        cp16(Kst + row * KSTR + c4, kTp + (size_t)row * TT + c4);
        cp16(Vs + row * VSTR + c4, Vp + (size_t)row * DD + c4);
    }
}

__global__ __launch_bounds__(256, 2)
void flash_tc_kernel(const float* __restrict__ Q,
                     const float* __restrict__ kT,
                     const float* __restrict__ Vg,
                     const int*   __restrict__ mask,
                     const float* __restrict__ xin,
                     float* __restrict__ out) {
    extern __shared__ float sm[];
    float* Qs  = sm;                    // [q][d]       stride QSTR
    float* Kst = Qs  + 64 * QSTR;       // 2x [d][kk]   stride KSTR
    float* Vs  = Kst + 2 * 64 * KSTR;   // 2x [kk][d]   stride VSTR
    float* Ss  = Vs  + 2 * 64 * VSTR;   // [q][kk]      stride SSTR
    float* m_row   = Ss + 64 * SSTR;
    float* l_row   = m_row + 64;
    float* c_row   = l_row + 64;
    float* any_row = c_row + 64;

    const int tid = threadIdx.x;
    const int warp = tid >> 5, lane = tid & 31;
    const int g = lane >> 2, t = lane & 3;
    const int wm = (warp & 3) << 4;     // 0,16,32,48
    const int wn = (warp >> 2) << 5;    // 0,32
    const int qt = blockIdx.x, h = blockIdx.y, b = blockIdx.z;
    const int q0 = qt * 64;

    const float* Qgp  = Q  + ((size_t)(b * TT + q0) * DD + h * DH);
    const float* kTbh = kT + (size_t)(b * HH + h) * DH * TT;

    // prologue: prefetch Q + K/V tile 0
#pragma unroll
    for (int i = 0; i < 4; i++) {
        int lin = tid + i * 256;
        int row = lin >> 4, c4 = (lin & 15) << 2;
        cp16(Qs + row * QSTR + c4, Qgp + (size_t)row * DD + c4);
    }
    fl_prefetch_kv(kTbh, Vg + ((size_t)(b * TT) * DD + h * DH), Kst, Vs, tid);
    asm volatile("cp.async.commit_group;");

    if (tid < 64) {
        m_row[tid] = -INFINITY;
        l_row[tid] = 0.f;
        any_row[tid] = 0.f;
    }
    float oacc[4][4];
#pragma unroll
    for (int nt = 0; nt < 4; nt++)
#pragma unroll
        for (int r = 0; r < 4; r++) oacc[nt][r] = 0.f;

    for (int kt = 0; kt < TT / 64; kt++) {
        const int bufi = kt & 1;
        const float* Kb = Kst + bufi * 64 * KSTR;
        const float* Vb = Vs + bufi * 64 * VSTR;

        asm volatile("cp.async.wait_group 0;");
        __syncthreads();
        if (kt + 1 < TT / 64) {
            const int k1 = (kt + 1) * 64;
            fl_prefetch_kv(kTbh + k1,
                           Vg + ((size_t)(b * TT + k1) * DD + h * DH),
                           Kst + (bufi ^ 1) * 64 * KSTR,
                           Vs + (bufi ^ 1) * 64 * VSTR, tid);
            asm volatile("cp.async.commit_group;");
        }

        // ---- S = Q K^T ----
        float sacc[4][4];
#pragma unroll
        for (int nt = 0; nt < 4; nt++)
#pragma unroll
            for (int r = 0; r < 4; r++) sacc[nt][r] = 0.f;
#pragma unroll
        for (int ks = 0; ks < 8; ks++) {
            const int kk = ks * 8;
            unsigned a[4];
            const float* ap = Qs + (wm + g) * QSTR + kk + t;
            a[0] = __float_as_uint(ap[0]);
            a[1] = __float_as_uint(ap[8 * QSTR]);
            a[2] = __float_as_uint(ap[4]);
            a[3] = __float_as_uint(ap[8 * QSTR + 4]);
#pragma unroll
            for (int nt = 0; nt < 4; nt++) {
                unsigned bv2[2];
                const float* bp = Kb + (kk + t) * KSTR + wn + nt * 8 + g;
                bv2[0] = __float_as_uint(bp[0]);
                bv2[1] = __float_as_uint(bp[4 * KSTR]);
                MMA_TF32(sacc[nt], a, bv2);
            }
        }
#pragma unroll
        for (int nt = 0; nt < 4; nt++) {
            int col = wn + nt * 8 + 2 * t;
            float2 s0 = {sacc[nt][0] * 0.125f, sacc[nt][1] * 0.125f};
            float2 s1 = {sacc[nt][2] * 0.125f, sacc[nt][3] * 0.125f};
            *reinterpret_cast<float2*>(Ss + (wm + g) * SSTR + col) = s0;
            *reinterpret_cast<float2*>(Ss + (wm + g + 8) * SSTR + col) = s1;
        }
        __syncthreads();

        // ---- online softmax (4 threads per row) ----
        {
            int r = tid >> 2, part = tid & 3;
            int ks0 = part * 16;
            const int k0 = kt * 64;
            const int4* mp = reinterpret_cast<const int4*>(
                mask + (size_t)b * TT * TT + (size_t)(q0 + r) * TT + k0 + ks0);
            int4 m0 = mp[0], m1 = mp[1], m2 = mp[2], m3 = mp[3];
            int mm[16] = {m0.x, m0.y, m0.z, m0.w, m1.x, m1.y, m1.z, m1.w,
                          m2.x, m2.y, m2.z, m2.w, m3.x, m3.y, m3.z, m3.w};
            float sv[16];
            float mx = -INFINITY;
            int anyl = 0;
#pragma unroll
            for (int k = 0; k < 16; k++) {
                float s = Ss[r * SSTR + ks0 + k] + (mm[k] ? 0.f : -1e9f);
                sv[k] = s;
                mx = fmaxf(mx, s);
                anyl |= mm[k];
            }
            mx = fmaxf(mx, __shfl_xor_sync(0xffffffffu, mx, 1));
            mx = fmaxf(mx, __shfl_xor_sync(0xffffffffu, mx, 2));
            float mold = m_row[r];
            float mnew = fmaxf(mold, mx);
            float psum = 0.f;
#pragma unroll
            for (int k = 0; k < 16; k++) {
                float e = __expf(sv[k] - mnew);
                Ss[r * SSTR + ks0 + k] = f2tf32(e);
                psum += e;
            }
            psum += __shfl_xor_sync(0xffffffffu, psum, 1);
            psum += __shfl_xor_sync(0xffffffffu, psum, 2);
            if (anyl) any_row[r] = 1.f;
            if (part == 0) {
                float c = __expf(mold - mnew);
                c_row[r] = c;
                l_row[r] = l_row[r] * c + psum;
                m_row[r] = mnew;
            }
        }
        __syncthreads();

        // ---- O = O*c + P @ V ----
        {
            float c0 = c_row[wm + g];
            float c1 = c_row[wm + g + 8];
#pragma unroll
            for (int nt = 0; nt < 4; nt++) {
                oacc[nt][0] *= c0; oacc[nt][1] *= c0;
                oacc[nt][2] *= c1; oacc[nt][3] *= c1;
            }
#pragma unroll
            for (int ks = 0; ks < 8; ks++) {
                const int kk = ks * 8;
                unsigned a[4];
                const float* ap = Ss + (wm + g) * SSTR + kk + t;
                a[0] = __float_as_uint(ap[0]);
                a[1] = __float_as_uint(ap[8 * SSTR]);
                a[2] = __float_as_uint(ap[4]);
                a[3] = __float_as_uint(ap[8 * SSTR + 4]);
#pragma unroll
                for (int nt = 0; nt < 4; nt++) {
                    unsigned bv2[2];
                    const float* bp = Vb + (kk + t) * VSTR + wn + nt * 8 + g;
                    bv2[0] = __float_as_uint(bp[0]);
                    bv2[1] = __float_as_uint(bp[4 * VSTR]);
                    MMA_TF32(oacc[nt], a, bv2);
                }
            }
        }
        __syncthreads();   // all reads of buf done before next prefetch overwrites
    }

    // ---- epilogue: normalize, zero fully-masked rows, add residual x ----
    {
        int r0 = wm + g, r1 = wm + g + 8;
        float inv0 = (any_row[r0] != 0.f) ? (1.f / l_row[r0]) : 0.f;
        float inv1 = (any_row[r1] != 0.f) ? (1.f / l_row[r1]) : 0.f;
#pragma unroll
        for (int nt = 0; nt < 4; nt++) {
            int col = h * DH + wn + nt * 8 + 2 * t;
            size_t base0 = (size_t)(b * TT + q0 + r0) * DD + col;
            size_t base1 = (size_t)(b * TT + q0 + r1) * DD + col;
            float2 x0 = *reinterpret_cast<const float2*>(xin + base0);
            float2 x1 = *reinterpret_cast<const float2*>(xin + base1);
            float2 o0 = {oacc[nt][0] * inv0 + x0.x, oacc[nt][1] * inv0 + x0.y};
            float2 o1 = {oacc[nt][2] * inv1 + x1.x, oacc[nt][3] * inv1 + x1.y};
            *reinterpret_cast<float2*>(out + base0) = o0;
            *reinterpret_cast<float2*>(out + base1) = o1;
        }
    }
}

// ---------------------------------------------------------------------------
// Launch
// ---------------------------------------------------------------------------
extern "C" void kernel_launch(void* const* d_in, const int* in_sizes, int n_in,
                              void* d_out, int out_size) {
    const float* x     = (const float*)d_in[0];
    const int*   mask  = (const int*)  d_in[1];
    const float* Wq    = (const float*)d_in[2];
    const float* bq    = (const float*)d_in[3];
    const float* Wk    = (const float*)d_in[4];
    const float* bk    = (const float*)d_in[5];
    const float* Wv    = (const float*)d_in[6];
    const float* bv    = (const float*)d_in[7];
    const float* g_in  = (const float*)d_in[8];
    const float* b_in  = (const float*)d_in[9];
    const float* g1    = (const float*)d_in[10];
    const float* b1    = (const float*)d_in[11];
    const float* W_ff1 = (const float*)d_in[12];
    const float* b_ff1 = (const float*)d_in[13];
    const float* W_ff2 = (const float*)d_in[14];
    const float* b_ff2 = (const float*)d_in[15];
    const float* g2    = (const float*)d_in[16];
    const float* b2    = (const float*)d_in[17];
    float* out = (float*)d_out;

    float *xn, *q, *k, *kT, *v, *res1, *h1n, *ff, *res2;
    float *wq_t, *wk_t, *wv_t, *w1_t, *w2_t;
    cudaGetSymbolAddress((void**)&xn,   g_xn);
    cudaGetSymbolAddress((void**)&q,    g_q);
    cudaGetSymbolAddress((void**)&k,    g_k);
    cudaGetSymbolAddress((void**)&kT,   g_kT);
    cudaGetSymbolAddress((void**)&v,    g_v);
    cudaGetSymbolAddress((void**)&res1, g_res1);
    cudaGetSymbolAddress((void**)&h1n,  g_h1n);
    cudaGetSymbolAddress((void**)&ff,   g_ff);
    cudaGetSymbolAddress((void**)&res2, g_res2);
    cudaGetSymbolAddress((void**)&wq_t, g_wq_t);
    cudaGetSymbolAddress((void**)&wk_t, g_wk_t);
    cudaGetSymbolAddress((void**)&wv_t, g_wv_t);
    cudaGetSymbolAddress((void**)&w1_t, g_w1_t);
    cudaGetSymbolAddress((void**)&w2_t, g_w2_t);

    const int flash_smem = FL_SMEM_FLOATS * sizeof(float);
    cudaFuncSetAttribute(flash_tc_kernel,
                         cudaFuncAttributeMaxDynamicSharedMemorySize, flash_smem);
    cudaFuncSetAttribute(tf32_gemm_kernel,
                         cudaFuncAttributeMaxDynamicSharedMemorySize, GEMM_SMEM);
    cudaFuncSetAttribute(tf32_gemm_qkv_kernel,
                         cudaFuncAttributeMaxDynamicSharedMemorySize, GEMM_SMEM);

    // 0. weight -> tf32 copies (2 launches)
    {
        CvtJobs jq;
        jq.in[0] = Wq; jq.in[1] = Wk; jq.in[2] = Wv;
        jq.out[0] = wq_t; jq.out[1] = wk_t; jq.out[2] = wv_t;
        int n4 = DD * DD / 4;
        cvt_tf32_multi_kernel<<<dim3((n4 + 255) / 256, 1, 3), 256>>>(jq, n4);
        CvtJobs jf;
        jf.in[0] = W_ff1; jf.in[1] = W_ff2; jf.in[2] = nullptr;
        jf.out[0] = w1_t; jf.out[1] = w2_t; jf.out[2] = nullptr;
        int m4 = DD * FFN / 4;
        cvt_tf32_multi_kernel<<<dim3((m4 + 255) / 256, 1, 2), 256>>>(jf, m4);
    }

    // 1. pre-LN (tf32-rounded output)
    ln1024_kernel<<<MROWS, 256>>>(x, g_in, b_in, xn, 1);

    // 2. QKV projections (fused grid.z; outputs tf32-rounded)
    {
        QkvPtrs p;
        p.W[0] = wq_t; p.W[1] = wk_t; p.W[2] = wv_t;
        p.b[0] = bq;   p.b[1] = bk;   p.b[2] = bv;
        p.o[0] = q;    p.o[1] = k;    p.o[2] = v;
        tf32_gemm_qkv_kernel<<<dim3(DD / BN, MROWS / BM, 3), 128, GEMM_SMEM>>>(xn, p);
    }

    // 2b. K -> kT for cp.async-able flash loads
    transpose_k_kernel<<<dim3(TT / 32, DD / 32, BB), dim3(32, 8)>>>(k, kT);

    // 3. attention + residual(x) -> res1
    flash_tc_kernel<<<dim3(TT / 64, HH, BB), 256, flash_smem>>>(q, kT, v, mask, x, res1);

    // 4. LN -> h1n (tf32-rounded)
    ln1024_kernel<<<MROWS, 256>>>(res1, g1, b1, h1n, 1);

    // 5. FF1 + relu (output tf32-rounded)
    tf32_gemm_kernel<<<dim3(FFN / BN, MROWS / BM), 128, GEMM_SMEM>>>(
        MROWS, FFN, DD, h1n, w1_t, b_ff1, nullptr, ff, 1, 1);

    // 6. FF2 + bias + residual(res1)
    tf32_gemm_kernel<<<dim3(DD / BN, MROWS / BM), 128, GEMM_SMEM>>>(
        MROWS, DD, FFN, ff, w2_t, b_ff2, res1, res2, 0, 0);

    // 7. final LN -> out
    ln1024_kernel<<<MROWS, 256>>>(res2, g2, b2, out, 0);
}